// round 9
// baseline (speedup 1.0000x reference)
#include <cuda_runtime.h>
#include <cuda_bf16.h>
#include <cuda_fp16.h>
#include <cstdint>

#define F_DIM 16
#define N_DIM 8192
#define D_DIM 64
#define K_DIM 512
#define THREADS 256
#define NUM_BLOCKS 128          // 16 f x 8 row-chunks
#define TILE_M 128
#define TILES 8                 // 1024 rows per block
#define OUT_ELEMS ((size_t)F_DIM * N_DIM * D_DIM)   // 8388608

// ---- smem layout (bytes) ----
#define SM_A 0                                  // bf16 A [128 rows][128B], SW128
#define SM_B 16384                              // bf16 B [512 rows(k-code)][128B], SW128
#define SM_S (SM_B + 65536)                     // fp16 scores [128][S_STRIDE_W words]
#define S_STRIDE_W 265                          // %32==9 -> <=2-way STS conflicts
#define SM_WNORM  (SM_S + 128 * S_STRIDE_W * 4)
#define SM_ROWMIN (SM_WNORM + K_DIM * 4)        // float [2][128]
#define SMEM_BYTES (SM_ROWMIN + 2 * 128 * 4)    // 220672

#define SW128(o) ((o) ^ (((o) >> 3) & 0x70))

// ---- global scratch (static, allowed) ----
__device__ float g_wT[F_DIM * K_DIM * D_DIM];   // [f][k][d] fp32, L2-resident
__device__ float g_wnorm[F_DIM * K_DIM];
__device__ float g_wmaxn[F_DIM];
__device__ float g_partials[NUM_BLOCKS];

// ---- helpers ----
__device__ __forceinline__ uint32_t smem_u32(const void* p) {
    uint32_t a;
    asm("{ .reg .u64 t; cvta.to.shared.u64 t, %1; cvt.u32.u64 %0, t; }" : "=r"(a) : "l"(p));
    return a;
}
__device__ __forceinline__ uint32_t bf2(float x, float y) {
    __nv_bfloat162 b = __float22bfloat162_rn(make_float2(x, y));
    return *(uint32_t*)&b;
}
__device__ __forceinline__ uint32_t h2pk(float a, float b) {
    __half2 h = __floats2half2_rn(a, b);
    return *(uint32_t*)&h;
}
// non-trans ldmatrix x4 (sm_75+; compiles for plain sm_103)
__device__ __forceinline__ void ldsm_x4(uint32_t* r, uint32_t addr) {
    asm volatile("ldmatrix.sync.aligned.m8n8.x4.shared.b16 {%0,%1,%2,%3}, [%4];"
                 : "=r"(r[0]), "=r"(r[1]), "=r"(r[2]), "=r"(r[3]) : "r"(addr));
}
// bf16 mma, fp32 accumulate (sm_80+)
__device__ __forceinline__ void mma_bf16(float* c, const uint32_t* a, const uint32_t* b) {
    asm volatile("mma.sync.aligned.m16n8k16.row.col.f32.bf16.bf16.f32 "
                 "{%0,%1,%2,%3}, {%4,%5,%6,%7}, {%8,%9}, {%0,%1,%2,%3};"
                 : "+f"(c[0]), "+f"(c[1]), "+f"(c[2]), "+f"(c[3])
                 : "r"(a[0]), "r"(a[1]), "r"(a[2]), "r"(a[3]), "r"(b[0]), "r"(b[1]));
}

// ======================= prep: wT, wnorm, wmax ==============================
__global__ void vq_prep(const float* __restrict__ w) {
    const int f = blockIdx.x;
    const int k = threadIdx.x;      // 512 threads
    const float* wf = w + (size_t)f * D_DIM * K_DIM;
    float buf[D_DIM];
    float wn = 0.f;
    #pragma unroll
    for (int d = 0; d < D_DIM; ++d) {
        float v = wf[d * K_DIM + k];    // coalesced over k
        buf[d] = v;
        wn = fmaf(v, v, wn);
    }
    float4* dst = (float4*)(g_wT + ((size_t)(f * K_DIM + k)) * D_DIM);
    #pragma unroll
    for (int j = 0; j < D_DIM / 4; ++j)
        dst[j] = make_float4(buf[4*j], buf[4*j+1], buf[4*j+2], buf[4*j+3]);
    g_wnorm[f * K_DIM + k] = wn;

    __shared__ float red[K_DIM];
    red[k] = wn;
    __syncthreads();
    #pragma unroll
    for (int s = K_DIM / 2; s > 0; s >>= 1) {
        if (k < s) red[k] = fmaxf(red[k], red[k + s]);
        __syncthreads();
    }
    if (k == 0) g_wmaxn[f] = red[0];
}

// ============================== main ========================================
__global__ __launch_bounds__(THREADS, 1)
void vq_main(const float* __restrict__ x_all, float* __restrict__ out) {
    extern __shared__ char smem[];
    const uint32_t sb = smem_u32(smem);
    float* wnorm    = (float*)(smem + SM_WNORM);
    uint32_t* S     = (uint32_t*)(smem + SM_S);
    float* rowmin   = (float*)(smem + SM_ROWMIN);   // [2][128]

    const int tid  = threadIdx.x;
    const int lane = tid & 31;
    const int wid  = tid >> 5;
    const int f = blockIdx.x >> 3;
    const int rowbase = (blockIdx.x & 7) * (TILES * TILE_M);

    // ---- stage B = w^T bf16 [512 k-rows x 64 d], SW128 (once per block) ----
    const float* wTf = g_wT + (size_t)f * K_DIM * D_DIM;
    for (int i = tid; i < K_DIM * 8; i += THREADS) {     // i = k*8 + j (16B chunk)
        int k = i >> 3, j = i & 7;
        float4 v0 = __ldg((const float4*)(wTf + k * 64 + j * 8));
        float4 v1 = __ldg((const float4*)(wTf + k * 64 + j * 8 + 4));
        uint4 pk = make_uint4(bf2(v0.x, v0.y), bf2(v0.z, v0.w),
                              bf2(v1.x, v1.y), bf2(v1.z, v1.w));
        *(uint4*)(smem + SM_B + SW128((uint32_t)(k * 128 + j * 16))) = pk;
    }
    for (int i = tid; i < K_DIM; i += THREADS) wnorm[i] = g_wnorm[f * K_DIM + i];
    const float wmaxn = g_wmaxn[f];

    const float* xg = x_all + (size_t)f * N_DIM * D_DIM;
    float* og = out + (size_t)f * N_DIM * D_DIM;

    const int nhalf = wid >> 2;     // which 256-code half this warp scores
    const int mq    = wid & 3;      // row quarter: rows 32*mq .. +31
    float loss_acc = 0.f;

    for (int t = 0; t < TILES; ++t) {
        // ---------- phase 1: stage A bf16 (2 threads per row) ----------
        {
            int row = tid >> 1, half = tid & 1;
            const float4* xr = (const float4*)(xg + (size_t)(rowbase + t * TILE_M + row) * D_DIM + half * 32);
            #pragma unroll
            for (int j = 0; j < 4; ++j) {
                float4 v0 = __ldg(xr + 2 * j), v1 = __ldg(xr + 2 * j + 1);
                uint4 pk = make_uint4(bf2(v0.x, v0.y), bf2(v0.z, v0.w),
                                      bf2(v1.x, v1.y), bf2(v1.z, v1.w));
                *(uint4*)(smem + SM_A + SW128((uint32_t)(row * 128 + half * 64 + j * 16))) = pk;
            }
        }
        __syncthreads();

        // ---------- phase 2: GEMM (mma.sync) + scores + row mins ----------
        {
            // A fragments: 2 m-tiles x 4 k-steps, non-trans ldmatrix
            uint32_t a[2][4][4];
            #pragma unroll
            for (int mt = 0; mt < 2; ++mt)
                #pragma unroll
                for (int ks = 0; ks < 4; ++ks) {
                    uint32_t off = (uint32_t)((mq * 32 + mt * 16 + (lane & 15)) * 128
                                              + ks * 32 + (lane >> 4) * 16);
                    ldsm_x4(a[mt][ks], sb + SM_A + SW128(off));
                }

            float mn[4] = {3.4e38f, 3.4e38f, 3.4e38f, 3.4e38f};
            #pragma unroll 4
            for (int nt = 0; nt < 32; ++nt) {
                const int n0 = nhalf * 256 + nt * 8;
                uint32_t b[8];   // [2ks]=k-lo, [2ks+1]=k-hi, non-trans of [n][k]
                uint32_t boff0 = (uint32_t)((n0 + (lane & 7)) * 128 + (lane >> 3) * 16);
                ldsm_x4(b,     sb + SM_B + SW128(boff0));
                ldsm_x4(b + 4, sb + SM_B + SW128(boff0 + 64));

                float c0[4] = {0, 0, 0, 0}, c1[4] = {0, 0, 0, 0};
                #pragma unroll
                for (int ks = 0; ks < 4; ++ks) {
                    mma_bf16(c0, a[0][ks], &b[2 * ks]);
                    mma_bf16(c1, a[1][ks], &b[2 * ks]);
                }

                const int col0 = n0 + 2 * (lane & 3);
                const float wn0 = wnorm[col0], wn1 = wnorm[col0 + 1];
                float s00 = fmaf(-2.f, c0[0], wn0), s01 = fmaf(-2.f, c0[1], wn1);
                float s02 = fmaf(-2.f, c0[2], wn0), s03 = fmaf(-2.f, c0[3], wn1);
                float s10 = fmaf(-2.f, c1[0], wn0), s11 = fmaf(-2.f, c1[1], wn1);
                float s12 = fmaf(-2.f, c1[2], wn0), s13 = fmaf(-2.f, c1[3], wn1);
                mn[0] = fminf(mn[0], fminf(s00, s01));
                mn[1] = fminf(mn[1], fminf(s02, s03));
                mn[2] = fminf(mn[2], fminf(s10, s11));
                mn[3] = fminf(mn[3], fminf(s12, s13));

                const int r0   = mq * 32 + (lane >> 2);
                const int wcol = (n0 >> 1) + (lane & 3);
                S[(r0)      * S_STRIDE_W + wcol] = h2pk(s00, s01);
                S[(r0 + 8)  * S_STRIDE_W + wcol] = h2pk(s02, s03);
                S[(r0 + 16) * S_STRIDE_W + wcol] = h2pk(s10, s11);
                S[(r0 + 24) * S_STRIDE_W + wcol] = h2pk(s12, s13);
            }

            // per-row min across the 4-lane quad
            #pragma unroll
            for (int i = 0; i < 4; ++i) {
                mn[i] = fminf(mn[i], __shfl_xor_sync(0xffffffffu, mn[i], 1));
                mn[i] = fminf(mn[i], __shfl_xor_sync(0xffffffffu, mn[i], 2));
            }
            if ((lane & 3) == 0) {
                const int r0 = mq * 32 + (lane >> 2);
                rowmin[nhalf * 128 + r0]      = mn[0];
                rowmin[nhalf * 128 + r0 + 8]  = mn[1];
                rowmin[nhalf * 128 + r0 + 16] = mn[2];
                rowmin[nhalf * 128 + r0 + 24] = mn[3];
            }
        }
        __syncthreads();

        // ---------- phase 3: scan + exact fp32 rescore (2 threads per row) ----------
        {
            const int rloc = tid >> 1, half = tid & 1;
            const int grow = rowbase + t * TILE_M + rloc;

            float4 xv[16];
            const float4* xr = (const float4*)(xg + (size_t)grow * D_DIM);
            float xn2 = 0.f;
            #pragma unroll
            for (int j = 0; j < 16; ++j) {
                float4 v = __ldg(xr + j);
                xv[j] = v;
                xn2 = fmaf(v.x, v.x, xn2); xn2 = fmaf(v.y, v.y, xn2);
                xn2 = fmaf(v.z, v.z, xn2); xn2 = fmaf(v.w, v.w, xn2);
            }
            const float m = fminf(rowmin[rloc], rowmin[128 + rloc]);
            // margin = 2x provable bf16-dot error bound + fp16-store slack
            const float margin = 0.03125f * sqrtf(xn2) * sqrtf(wmaxn) + 0.125f;
            const float th = m + margin;
            const __half2 th2 = __floats2half2_rn(th, th);

            float bests = 3.4e38f;
            int   bestk = K_DIM;    // sentinel (empty half)
            const uint32_t* Srow = S + rloc * S_STRIDE_W + half * 128;
            for (int wi = 0; wi < 128; ++wi) {
                uint32_t u = Srow[wi];
                __half2 hv = *(__half2*)&u;
                __half2 le = __hle2(hv, th2);
                if (*(uint32_t*)&le) {
                    float lo = __low2float(hv), hi = __high2float(hv);
                    #pragma unroll
                    for (int hh = 0; hh < 2; ++hh) {
                        float sv = hh ? hi : lo;
                        if (sv <= th) {
                            const int k = half * 256 + 2 * wi + hh;
                            const float4* wr = (const float4*)(g_wT + ((size_t)(f * K_DIM + k)) * D_DIM);
                            float dot = 0.f;
                            #pragma unroll
                            for (int j = 0; j < 16; ++j) {
                                float4 wv = __ldg(wr + j);
                                dot = fmaf(xv[j].x, wv.x, dot); dot = fmaf(xv[j].y, wv.y, dot);
                                dot = fmaf(xv[j].z, wv.z, dot); dot = fmaf(xv[j].w, wv.w, dot);
                            }
                            float se = fmaf(-2.f, dot, wnorm[k]);
                            if (se < bests) { bests = se; bestk = k; }   // first-min in-half
                        }
                    }
                }
            }
            // combine across the lane pair; equal exact score -> lower k (reference tie-break)
            {
                float os = __shfl_xor_sync(0xffffffffu, bests, 1);
                int   ok = __shfl_xor_sync(0xffffffffu, bestk, 1);
                if (os < bests || (os == bests && ok < bestk)) { bests = os; bestk = ok; }
            }
            // write this thread's half of the winning code (exact fp32)
            const float4* wr = (const float4*)(g_wT + ((size_t)(f * K_DIM + bestk)) * D_DIM) + half * 8;
            float4* o = (float4*)(og + (size_t)grow * D_DIM) + half * 8;
            #pragma unroll
            for (int j = 0; j < 8; ++j) o[j] = __ldg(wr + j);
            // loss: exact sum of squared diffs for the winner (half 0 only)
            if (half == 0) {
                const float4* wfull = (const float4*)(g_wT + ((size_t)(f * K_DIM + bestk)) * D_DIM);
                float acc = 0.f;
                #pragma unroll
                for (int j = 0; j < 16; ++j) {
                    float4 wv = __ldg(wfull + j);
                    float d0 = xv[j].x - wv.x, d1 = xv[j].y - wv.y;
                    float d2 = xv[j].z - wv.z, d3 = xv[j].w - wv.w;
                    acc = fmaf(d0, d0, acc); acc = fmaf(d1, d1, acc);
                    acc = fmaf(d2, d2, acc); acc = fmaf(d3, d3, acc);
                }
                loss_acc += acc;
            }
        }
        __syncthreads();
    }

    // deterministic block loss reduction (reuse score smem)
    float* red = (float*)(smem + SM_S);
    red[tid] = loss_acc;
    __syncthreads();
    #pragma unroll
    for (int s = THREADS / 2; s > 0; s >>= 1) {
        if (tid < s) red[tid] += red[tid + s];
        __syncthreads();
    }
    if (tid == 0) g_partials[blockIdx.x] = red[0];
}

// ============================ finalize ======================================
__global__ void vq_finalize(float* out, int write_loss) {
    __shared__ float red[NUM_BLOCKS];
    int t = threadIdx.x;
    red[t] = g_partials[t];
    __syncthreads();
    #pragma unroll
    for (int s = NUM_BLOCKS / 2; s > 0; s >>= 1) {
        if (t < s) red[t] += red[t + s];
        __syncthreads();
    }
    if (t == 0 && write_loss) {
        // loss = q_latent + 0.25 * e_latent = 1.25 * mean((q - x)^2)
        out[OUT_ELEMS] = 1.25f * red[0] / (float)OUT_ELEMS;
    }
}

extern "C" void kernel_launch(void* const* d_in, const int* in_sizes, int n_in,
                              void* d_out, int out_size) {
    const float* x = (const float*)d_in[0];
    const float* w = (const float*)d_in[1];
    float* out = (float*)d_out;

    cudaFuncSetAttribute(vq_main, cudaFuncAttributeMaxDynamicSharedMemorySize,
                         (int)SMEM_BYTES);

    vq_prep<<<F_DIM, K_DIM>>>(w);
    vq_main<<<NUM_BLOCKS, THREADS, SMEM_BYTES>>>(x, out);

    int write_loss = (out_size > (int)OUT_ELEMS) ? 1 : 0;
    vq_finalize<<<1, NUM_BLOCKS>>>(out, write_loss);
}